// round 15
// baseline (speedup 1.0000x reference)
#include <cuda_runtime.h>

#define NN 32
#define CC 64
#define TT 400
#define VV 27
#define SS 2
#define OO 64
#define LEAKK 0.1f
#define EPSS 1e-5f

#define TCH 25            // t-chunks for kernel A (16 t each, 8 pairs)
#define TBD 6             // t per block, kernel D
#define NBD ((TT + TBD - 1)/TBD)   // 67

typedef unsigned long long ull;

__device__ __forceinline__ ull fma2(ull a, ull b, ull c) {
    ull d;
    asm("fma.rn.f32x2 %0, %1, %2, %3;" : "=l"(d) : "l"(a), "l"(b), "l"(c));
    return d;
}
__device__ __forceinline__ ull pk(float lo, float hi) {
    ull r;
    asm("mov.b64 %0, {%1, %2};" : "=l"(r) : "f"(lo), "f"(hi));
    return r;
}
__device__ __forceinline__ void upk(ull v, float& lo, float& hi) {
    asm("mov.b64 {%0, %1}, %2;" : "=f"(lo), "=f"(hi) : "l"(v));
}
// 16B shared load of two packed pairs
__device__ __forceinline__ ulonglong2 lds128(const ull* p) {
    return *reinterpret_cast<const ulonglong2*>(p);
}

// Scratch (static device globals — allocation-free)
__device__ float g_att_part[NN*TCH*SS*VV*VV];
__device__ float g_att[NN*SS*VV*VV];
__device__ float g_y2[(size_t)NN*TT*1792];      // [n][t][c*28+v], padded

// ---------------------------------------------------------------------------
// Kernel A: y = x + pe ; qk = W_in*y + b_in ; partial att accum over 16 t
// grid (25, NN), 512 threads (16 og x 4 outputs). Packed over t-pairs.
// ---------------------------------------------------------------------------
__global__ void __launch_bounds__(512,2) k_att_part(const float* __restrict__ x,
                                                    const float* __restrict__ pe,
                                                    const float* __restrict__ W_in,
                                                    const float* __restrict__ b_in) {
    extern __shared__ ull smU[];
    ull* sW2  = smU;            // 4096  (dup W_in, [c][o])
    ull* sy2  = sW2 + 4096;     // 1792  ([c][v] t-pair)
    ull* sqk2 = sy2 + 1792;     // 1792  ([o][v] t-pair)
    float* sb = (float*)(sqk2 + 1792);  // 64

    int n = blockIdx.y, chunk = blockIdx.x;
    int tid = threadIdx.x, og = tid >> 5, vv = tid & 31;

    for (int i = tid; i < 4096; i += 512) {
        int o = i & 63, c = i >> 6;
        float w = W_in[o*64 + c];
        sW2[i] = pk(w, w);
    }
    if (tid < 64) sb[tid] = b_in[tid];

    // att tiles: 2 s * 14 u2 * 14 v2 = 392 tiles of 2x2 (u,v); one per thread
    ull accA[4] = {0,0,0,0};
    int tileA = tid;                 // valid < 392
    int sA = tileA / 196; int rA = tileA - sA*196;
    int uA = (rA/14)*2, vA = (rA%14)*2;

    __syncthreads();

    for (int it = 0; it < 8; ++it) {
        int t0 = chunk*16 + it*2;
        for (int i = tid; i < 3456; i += 512) {
            int c = i / 54, r = i - c*54, tt = r / 27, v = r - tt*27;
            float val = x[(((size_t)n*64 + c)*400 + t0 + tt)*27 + v]
                      + pe[((size_t)c*400 + t0 + tt)*27 + v];
            ((float*)sy2)[2*(c*28 + v) + tt] = val;
        }
        __syncthreads();

        // projection: qk[o][vv] packed pair; 4 outputs per thread
        if (vv < 27) {
            ull acc[4];
            #pragma unroll
            for (int io = 0; io < 4; ++io) { float b = sb[og*4+io]; acc[io] = pk(b, b); }
            #pragma unroll 4
            for (int c = 0; c < 64; ++c) {
                ull yp = sy2[c*28 + vv];
                const ull* wrow = sW2 + c*64 + og*4;     // 16B-aligned
                ulonglong2 wA = lds128(wrow);
                ulonglong2 wB = lds128(wrow + 2);
                acc[0] = fma2(wA.x, yp, acc[0]);
                acc[1] = fma2(wA.y, yp, acc[1]);
                acc[2] = fma2(wB.x, yp, acc[2]);
                acc[3] = fma2(wB.y, yp, acc[3]);
            }
            #pragma unroll
            for (int io = 0; io < 4; ++io) sqk2[(og*4+io)*28 + vv] = acc[io];
        } else if (vv == 27) {
            // zero pad column so u+1 / v+1 loads are safe
            #pragma unroll
            for (int io = 0; io < 4; ++io) sqk2[(og*4+io)*28 + 27] = 0ULL;
        }
        __syncthreads();

        // q.k per 2x2 (u,v) tile; uA/vA even so pairs are 16B-aligned
        if (tileA < 392) {
            const ull* q  = sqk2 + (sA*16)*28;
            const ull* kk = sqk2 + (32 + sA*16)*28;
            #pragma unroll 4
            for (int c = 0; c < 16; ++c) {
                ulonglong2 qp = lds128(q  + c*28 + uA);
                ulonglong2 kp = lds128(kk + c*28 + vA);
                accA[0] = fma2(qp.x, kp.x, accA[0]); accA[1] = fma2(qp.x, kp.y, accA[1]);
                accA[2] = fma2(qp.y, kp.x, accA[2]); accA[3] = fma2(qp.y, kp.y, accA[3]);
            }
        }
        __syncthreads();
    }

    // horizontal-reduce pairs and store partials
    if (tileA < 392) {
        float* base = g_att_part + (((size_t)n*TCH + chunk)*SS + sA)*729;
        float a0,b0; upk(accA[0],a0,b0); base[uA*27+vA] = a0+b0;
        float a1,b1; upk(accA[1],a1,b1);
        float a2,b2; upk(accA[2],a2,b2);
        float a3,b3; upk(accA[3],a3,b3);
        if (vA+1 < 27)              base[uA*27+vA+1]     = a1+b1;
        if (uA+1 < 27)              base[(uA+1)*27+vA]   = a2+b2;
        if (uA+1 < 27 && vA+1 < 27) base[(uA+1)*27+vA+1] = a3+b3;
    }
}

// ---------------------------------------------------------------------------
// Kernel B: reduce chunks + tanh/alpha/att0
// ---------------------------------------------------------------------------
__global__ void __launch_bounds__(256) k_att_final(const float* __restrict__ alphas,
                                                   const float* __restrict__ att0) {
    int idx = blockIdx.x*256 + threadIdx.x;
    if (idx >= NN*SS*729) return;
    int n = idx / (SS*729);
    int r = idx - n*(SS*729);
    int s = r / 729;
    int uv = r - s*729;
    float sum = 0.f;
    #pragma unroll
    for (int ch = 0; ch < TCH; ++ch)
        sum += g_att_part[(((size_t)n*TCH + ch)*SS + s)*729 + uv];
    g_att[idx] = tanhf(sum * (1.0f/6400.f)) * alphas[s] + att0[s*729 + uv];
}

// ---------------------------------------------------------------------------
// Kernel C: xa = x@att ; h = lrelu(x + bn(W_out xa)) ; y2 = lrelu(x + bn(W_ff h))
// grid (200, NN), 512 threads, 2 t per block.
// x staged TRANSPOSED [u][c] (t-pair packed, row stride 66 -> 16B-aligned);
// xa/h stored as DUPLICATED f32x2 pairs, produced per-s (s-split) so the
// duplicated buffer is only 64 j wide and smem stays at 2 CTAs/SM.
// W inner loop: 2 LDS.64 acts + 1 LDS.128 weights + 4 fma2 per 8 MAC.
// ---------------------------------------------------------------------------
__global__ void __launch_bounds__(512,2) k_main(const float* __restrict__ x,
        const float* __restrict__ W_out, const float* __restrict__ b_out,
        const float* __restrict__ g_out, const float* __restrict__ be_out,
        const float* __restrict__ m_out, const float* __restrict__ v_out,
        const float* __restrict__ W_ff,  const float* __restrict__ b_ff,
        const float* __restrict__ g_ff,  const float* __restrict__ be_ff,
        const float* __restrict__ m_ff,  const float* __restrict__ v_ff) {
    extern __shared__ ull smU[];
    ull* sWoP = smU;                      // 4096  [j=128][op=32] pk{W[2op][j],W[2op+1][j]}
    ull* sWfP = sWoP + 4096;              // 2048  [j=64][op=32]
    ull* sx2T = sWfP + 2048;              // 1848  [u(27) rows of 66][c=64] pk{x[t0],x[t1]}
    ull* sxaD = sx2T + 1848;              // 3584  [jl=64][tt=2][v=28] duplicated pairs
    float* satt = (float*)(sxaD + 3584);  // 1458
    float* sscale_o = satt + 1458;
    float* sshift_o = sscale_o + 64;
    float* sscale_f = sshift_o + 64;
    float* sshift_f = sscale_f + 64;

    int n = blockIdx.y, tb = blockIdx.x;
    int tid = threadIdx.x, og = tid >> 5, vv = tid & 31;
    int t0 = tb*2;

    for (int idx = tid; idx < 4096; idx += 512) {
        int op = idx & 31, j = idx >> 5;
        sWoP[idx] = pk(W_out[(2*op)*128 + j], W_out[(2*op+1)*128 + j]);
    }
    for (int idx = tid; idx < 2048; idx += 512) {
        int op = idx & 31, j = idx >> 5;
        sWfP[idx] = pk(W_ff[(2*op)*64 + j], W_ff[(2*op+1)*64 + j]);
    }
    for (int i = tid; i < 1458; i += 512) satt[i] = g_att[(size_t)n*1458 + i];
    if (tid < 64) {
        float sc = g_out[tid]*rsqrtf(v_out[tid]+EPSS);
        sscale_o[tid] = sc;
        sshift_o[tid] = be_out[tid] + sc*(b_out[tid]-m_out[tid]);
        float sf = g_ff[tid]*rsqrtf(v_ff[tid]+EPSS);
        sscale_f[tid] = sf;
        sshift_f[tid] = be_ff[tid] + sf*(b_ff[tid]-m_ff[tid]);
    }
    // stage x transposed + t-pair packed: sx2T[u*66+c] = {x[c][t0], x[c][t0+1]}
    for (int i = tid; i < 3456; i += 512) {
        int c = i / 54, r = i - c*54, tt = r / 27, u = r - tt*27;
        ((float*)sx2T)[2*(u*66+c) + tt] = x[(((size_t)n*64 + c)*400 + t0 + tt)*27 + u];
    }
    __syncthreads();

    ull acc[2][2] = {};         // W_out accumulators persist across both s phases
    int c0 = og*4;              // this thread's 4 c (xa) / 4 o (W stages)

    #pragma unroll
    for (int s = 0; s < 2; ++s) {
        // xa phase: 4 c per thread; x via LDS.128 (uniform), att per-lane
        if (vv < 27) {
            ull a[4] = {};
            #pragma unroll 3
            for (int u = 0; u < 27; ++u) {
                float av = satt[s*729 + u*27 + vv];
                ull av2 = pk(av, av);
                const ull* xr = sx2T + u*66 + c0;   // even index -> 16B-aligned
                ulonglong2 xA = lds128(xr);
                ulonglong2 xB = lds128(xr + 2);
                a[0] = fma2(xA.x, av2, a[0]);
                a[1] = fma2(xA.y, av2, a[1]);
                a[2] = fma2(xB.x, av2, a[2]);
                a[3] = fma2(xB.y, av2, a[3]);
            }
            #pragma unroll
            for (int ci = 0; ci < 4; ++ci) {
                int jl = c0 + ci;
                float f0, f1; upk(a[ci], f0, f1);
                sxaD[(jl*2+0)*28 + vv] = pk(f0, f0);
                sxaD[(jl*2+1)*28 + vv] = pk(f1, f1);
            }
        }
        __syncthreads();

        // W_out partial over this s's 64 j
        if (vv < 27) {
            const ull* wbase = sWoP + (s*64)*32 + og*2;
            #pragma unroll 4
            for (int jl = 0; jl < 64; ++jl) {
                ull a0 = sxaD[(jl*2)*28 + vv], a1 = sxaD[(jl*2+1)*28 + vv];
                ulonglong2 w = lds128(wbase + jl*32);   // og*2 even -> 16B-aligned
                acc[0][0] = fma2(w.x, a0, acc[0][0]);
                acc[0][1] = fma2(w.x, a1, acc[0][1]);
                acc[1][0] = fma2(w.y, a0, acc[1][0]);
                acc[1][1] = fma2(w.y, a1, acc[1][1]);
            }
        }
        __syncthreads();        // reads done before next xa phase overwrites sxaD
    }

    // W_out epilogue -> h (duplicated pairs back into sxaD)
    float hv[2][2][2];          // [opl][tt][even/odd o]
    if (vv < 27) {
        #pragma unroll
        for (int opl = 0; opl < 2; ++opl) {
            int o0 = c0 + opl*2;
            float x00, x01, x10, x11;
            upk(sx2T[vv*66 + o0],     x00, x01);   // {x[o0][t0], x[o0][t1]}
            upk(sx2T[vv*66 + o0 + 1], x10, x11);
            float sc0 = sscale_o[o0],   sh0 = sshift_o[o0];
            float sc1 = sscale_o[o0+1], sh1 = sshift_o[o0+1];
            #pragma unroll
            for (int tt = 0; tt < 2; ++tt) {
                float f0, f1; upk(acc[opl][tt], f0, f1);
                float xv0 = (tt == 0) ? x00 : x01;
                float xv1 = (tt == 0) ? x10 : x11;
                float v0 = xv0 + f0*sc0 + sh0; v0 = fmaxf(v0, LEAKK*v0);
                float v1 = xv1 + f1*sc1 + sh1; v1 = fmaxf(v1, LEAKK*v1);
                hv[opl][tt][0] = v0; hv[opl][tt][1] = v1;
            }
        }
        #pragma unroll
        for (int opl = 0; opl < 2; ++opl) {
            int o0 = c0 + opl*2;
            #pragma unroll
            for (int tt = 0; tt < 2; ++tt) {
                sxaD[(o0*2+tt)*28 + vv]     = pk(hv[opl][tt][0], hv[opl][tt][0]);
                sxaD[((o0+1)*2+tt)*28 + vv] = pk(hv[opl][tt][1], hv[opl][tt][1]);
            }
        }
    }
    __syncthreads();

    // W_ff stage -> y2 (global)
    if (vv < 27) {
        ull accf[2][2] = {};
        const ull* wbase = sWfP + og*2;
        #pragma unroll 4
        for (int jl = 0; jl < 64; ++jl) {
            ull a0 = sxaD[(jl*2)*28 + vv], a1 = sxaD[(jl*2+1)*28 + vv];
            ulonglong2 w = lds128(wbase + jl*32);
            accf[0][0] = fma2(w.x, a0, accf[0][0]);
            accf[0][1] = fma2(w.x, a1, accf[0][1]);
            accf[1][0] = fma2(w.y, a0, accf[1][0]);
            accf[1][1] = fma2(w.y, a1, accf[1][1]);
        }
        #pragma unroll
        for (int opl = 0; opl < 2; ++opl) {
            int o0 = c0 + opl*2;
            float x00, x01, x10, x11;
            upk(sx2T[vv*66 + o0],     x00, x01);
            upk(sx2T[vv*66 + o0 + 1], x10, x11);
            float sc0 = sscale_f[o0],   sh0 = sshift_f[o0];
            float sc1 = sscale_f[o0+1], sh1 = sshift_f[o0+1];
            #pragma unroll
            for (int tt = 0; tt < 2; ++tt) {
                float f0, f1; upk(accf[opl][tt], f0, f1);
                float xv0 = (tt == 0) ? x00 : x01;
                float xv1 = (tt == 0) ? x10 : x11;
                float v0 = xv0 + f0*sc0 + sh0; v0 = fmaxf(v0, LEAKK*v0);
                float v1 = xv1 + f1*sc1 + sh1; v1 = fmaxf(v1, LEAKK*v1);
                size_t row = (size_t)(n*400 + t0 + tt)*1792;
                g_y2[row + o0*28 + vv]     = v0;
                g_y2[row + (o0+1)*28 + vv] = v1;
            }
        }
    }
}

// ---------------------------------------------------------------------------
// Kernel D: z = lrelu(y2 + bn(conv_t(y2) + b_t)); 6 t per block, o-packed.
// grid (67, NN), 512 threads. Weight opl-pair fused to LDS.128 per tap.
// ---------------------------------------------------------------------------
__global__ void __launch_bounds__(512,2) k_temporal(const float* __restrict__ W_t,
        const float* __restrict__ b_t, const float* __restrict__ g_t,
        const float* __restrict__ be_t, const float* __restrict__ m_t,
        const float* __restrict__ v_t, float* __restrict__ out) {
    extern __shared__ ull smU[];
    ull* sWtP = smU;                        // 6144  ([(i*3+tap)][op] o-pairs)
    float* tile   = (float*)(sWtP + 6144);  // 8 * 1792
    float* sscale = tile + 8*1792;
    float* sshift = sscale + 64;

    int n = blockIdx.y, tb = blockIdx.x;
    int tid = threadIdx.x, og = tid >> 5, vv = tid & 31;
    int t0 = tb*TBD;

    for (int idx = tid; idx < 6144; idx += 512) {
        int op = idx & 31, r = idx >> 5;     // r = i*3+tap
        sWtP[idx] = pk(W_t[(2*op)*192 + r], W_t[(2*op+1)*192 + r]);
    }
    if (tid < 64) {
        float sc = g_t[tid]*rsqrtf(v_t[tid]+EPSS);
        sscale[tid] = sc;
        sshift[tid] = be_t[tid] + sc*(b_t[tid]-m_t[tid]);
    }
    #pragma unroll
    for (int k = 0; k < TBD+2; ++k) {
        int t = t0 - 1 + k;
        ull* dst = (ull*)(tile + k*1792);
        if (t >= 0 && t < 400) {
            const ull* src = (const ull*)(g_y2 + ((size_t)n*400 + t)*1792);
            for (int i = tid; i < 896; i += 512) dst[i] = src[i];
        } else {
            for (int i = tid; i < 896; i += 512) dst[i] = 0ULL;
        }
    }
    __syncthreads();

    if (vv < 27) {
        ull acc[2][TBD] = {};
        #pragma unroll 2
        for (int i = 0; i < 64; ++i) {
            ull bp[TBD+2];
            #pragma unroll
            for (int k = 0; k < TBD+2; ++k) {
                float a = tile[k*1792 + i*28 + vv];
                bp[k] = pk(a, a);
            }
            // per tap: one LDS.128 yields both opl weights (16B-aligned: og*2 even)
            #pragma unroll
            for (int tap = 0; tap < 3; ++tap) {
                ulonglong2 w = lds128(sWtP + (i*3+tap)*32 + og*2);
                #pragma unroll
                for (int tt = 0; tt < TBD; ++tt) {
                    acc[0][tt] = fma2(w.x, bp[tap+tt], acc[0][tt]);
                    acc[1][tt] = fma2(w.y, bp[tap+tt], acc[1][tt]);
                }
            }
        }
        #pragma unroll
        for (int opl = 0; opl < 2; ++opl) {
            int o0 = og*4 + opl*2;
            float sc0 = sscale[o0],   sh0 = sshift[o0];
            float sc1 = sscale[o0+1], sh1 = sshift[o0+1];
            size_t ob0 = ((size_t)n*64 + o0)*400;
            size_t ob1 = ((size_t)n*64 + o0+1)*400;
            #pragma unroll
            for (int tt = 0; tt < TBD; ++tt) {
                if (t0 + tt >= 400) break;
                float f0, f1; upk(acc[opl][tt], f0, f1);
                float y0 = tile[(tt+1)*1792 + o0*28 + vv];
                float y1 = tile[(tt+1)*1792 + (o0+1)*28 + vv];
                float v0 = y0 + f0*sc0 + sh0; v0 = fmaxf(v0, LEAKK*v0);
                float v1 = y1 + f1*sc1 + sh1; v1 = fmaxf(v1, LEAKK*v1);
                out[(ob0 + t0 + tt)*27 + vv] = v0;
                out[(ob1 + t0 + tt)*27 + vv] = v1;
            }
        }
    }
}

// ---------------------------------------------------------------------------
extern "C" void kernel_launch(void* const* d_in, const int* in_sizes, int n_in,
                              void* d_out, int out_size) {
    const float* x      = (const float*)d_in[0];
    const float* pe     = (const float*)d_in[1];
    const float* W_in   = (const float*)d_in[2];
    const float* b_in   = (const float*)d_in[3];
    const float* alphas = (const float*)d_in[4];
    const float* att0   = (const float*)d_in[5];
    const float* W_out  = (const float*)d_in[6];
    const float* b_out  = (const float*)d_in[7];
    const float* g_out  = (const float*)d_in[8];
    const float* be_out = (const float*)d_in[9];
    const float* m_out  = (const float*)d_in[10];
    const float* v_out  = (const float*)d_in[11];
    const float* W_ff   = (const float*)d_in[12];
    const float* b_ff   = (const float*)d_in[13];
    const float* g_ff   = (const float*)d_in[14];
    const float* be_ff  = (const float*)d_in[15];
    const float* m_ff   = (const float*)d_in[16];
    const float* v_ff   = (const float*)d_in[17];
    const float* W_t    = (const float*)d_in[18];
    const float* b_t    = (const float*)d_in[19];
    const float* g_t    = (const float*)d_in[20];
    const float* be_t   = (const float*)d_in[21];
    const float* m_t    = (const float*)d_in[22];
    const float* v_t    = (const float*)d_in[23];
    float* out = (float*)d_out;

    const int smemA = 7680*8 + 64*4;                               // 61,696 B
    const int smemC = (4096+2048+1848+3584)*8 + (1458+256)*4;      //  99,464 B
    const int smemD = 6144*8 + (8*1792 + 128)*4;                   // 107,008 B
    cudaFuncSetAttribute(k_att_part, cudaFuncAttributeMaxDynamicSharedMemorySize, smemA);
    cudaFuncSetAttribute(k_main,     cudaFuncAttributeMaxDynamicSharedMemorySize, smemC);
    cudaFuncSetAttribute(k_temporal, cudaFuncAttributeMaxDynamicSharedMemorySize, smemD);

    k_att_part<<<dim3(TCH, NN), 512, smemA>>>(x, pe, W_in, b_in);
    k_att_final<<<(NN*SS*729 + 255)/256, 256>>>(alphas, att0);
    k_main<<<dim3(TT/2, NN), 512, smemC>>>(x, W_out, b_out, g_out, be_out, m_out, v_out,
                                           W_ff, b_ff, g_ff, be_ff, m_ff, v_ff);
    k_temporal<<<dim3(NBD, NN), 512, smemD>>>(W_t, b_t, g_t, be_t, m_t, v_t, out);
}

// round 16
// speedup vs baseline: 1.1280x; 1.1280x over previous
#include <cuda_runtime.h>

#define NN 32
#define CC 64
#define TT 400
#define VV 27
#define SS 2
#define OO 64
#define LEAKK 0.1f
#define EPSS 1e-5f

#define TCH 25            // t-chunks for kernel A (16 t each, 8 pairs)
#define TBD 6             // t per block, kernel D
#define NBD ((TT + TBD - 1)/TBD)   // 67

typedef unsigned long long ull;

__device__ __forceinline__ ull fma2(ull a, ull b, ull c) {
    ull d;
    asm("fma.rn.f32x2 %0, %1, %2, %3;" : "=l"(d) : "l"(a), "l"(b), "l"(c));
    return d;
}
__device__ __forceinline__ ull pk(float lo, float hi) {
    ull r;
    asm("mov.b64 %0, {%1, %2};" : "=l"(r) : "f"(lo), "f"(hi));
    return r;
}
__device__ __forceinline__ void upk(ull v, float& lo, float& hi) {
    asm("mov.b64 {%0, %1}, %2;" : "=f"(lo), "=f"(hi) : "l"(v));
}
// 16B shared load of two packed pairs
__device__ __forceinline__ ulonglong2 lds128(const ull* p) {
    return *reinterpret_cast<const ulonglong2*>(p);
}

// Scratch (static device globals — allocation-free)
__device__ float g_att_part[NN*TCH*SS*VV*VV];
__device__ float g_att[NN*SS*VV*VV];
__device__ float g_y2[(size_t)NN*TT*1792];      // [n][t][c*28+v], padded

// ---------------------------------------------------------------------------
// Kernel A: y = x + pe ; qk = W_in*y + b_in ; partial att accum over 16 t
// grid (25, NN), 512 threads (16 og x 4 outputs). Packed over t-pairs.
// ---------------------------------------------------------------------------
__global__ void __launch_bounds__(512,2) k_att_part(const float* __restrict__ x,
                                                    const float* __restrict__ pe,
                                                    const float* __restrict__ W_in,
                                                    const float* __restrict__ b_in) {
    extern __shared__ ull smU[];
    ull* sW2  = smU;            // 4096  (dup W_in, [c][o])
    ull* sy2  = sW2 + 4096;     // 1792  ([c][v] t-pair)
    ull* sqk2 = sy2 + 1792;     // 1792  ([o][v] t-pair)
    float* sb = (float*)(sqk2 + 1792);  // 64

    int n = blockIdx.y, chunk = blockIdx.x;
    int tid = threadIdx.x, og = tid >> 5, vv = tid & 31;

    for (int i = tid; i < 4096; i += 512) {
        int o = i & 63, c = i >> 6;
        float w = W_in[o*64 + c];
        sW2[i] = pk(w, w);
    }
    if (tid < 64) sb[tid] = b_in[tid];

    // att tiles: 2 s * 14 u2 * 14 v2 = 392 tiles of 2x2 (u,v); one per thread
    ull accA[4] = {0,0,0,0};
    int tileA = tid;                 // valid < 392
    int sA = tileA / 196; int rA = tileA - sA*196;
    int uA = (rA/14)*2, vA = (rA%14)*2;

    __syncthreads();

    for (int it = 0; it < 8; ++it) {
        int t0 = chunk*16 + it*2;
        for (int i = tid; i < 3456; i += 512) {
            int c = i / 54, r = i - c*54, tt = r / 27, v = r - tt*27;
            float val = x[(((size_t)n*64 + c)*400 + t0 + tt)*27 + v]
                      + pe[((size_t)c*400 + t0 + tt)*27 + v];
            ((float*)sy2)[2*(c*28 + v) + tt] = val;
        }
        __syncthreads();

        // projection: qk[o][vv] packed pair; 4 outputs per thread
        if (vv < 27) {
            ull acc[4];
            #pragma unroll
            for (int io = 0; io < 4; ++io) { float b = sb[og*4+io]; acc[io] = pk(b, b); }
            #pragma unroll 4
            for (int c = 0; c < 64; ++c) {
                ull yp = sy2[c*28 + vv];
                const ull* wrow = sW2 + c*64 + og*4;     // 16B-aligned
                ulonglong2 wA = lds128(wrow);
                ulonglong2 wB = lds128(wrow + 2);
                acc[0] = fma2(wA.x, yp, acc[0]);
                acc[1] = fma2(wA.y, yp, acc[1]);
                acc[2] = fma2(wB.x, yp, acc[2]);
                acc[3] = fma2(wB.y, yp, acc[3]);
            }
            #pragma unroll
            for (int io = 0; io < 4; ++io) sqk2[(og*4+io)*28 + vv] = acc[io];
        } else if (vv == 27) {
            // zero pad column so u+1 / v+1 loads are safe
            #pragma unroll
            for (int io = 0; io < 4; ++io) sqk2[(og*4+io)*28 + 27] = 0ULL;
        }
        __syncthreads();

        // q.k per 2x2 (u,v) tile; uA/vA even so pairs are 16B-aligned
        if (tileA < 392) {
            const ull* q  = sqk2 + (sA*16)*28;
            const ull* kk = sqk2 + (32 + sA*16)*28;
            #pragma unroll 4
            for (int c = 0; c < 16; ++c) {
                ulonglong2 qp = lds128(q  + c*28 + uA);
                ulonglong2 kp = lds128(kk + c*28 + vA);
                accA[0] = fma2(qp.x, kp.x, accA[0]); accA[1] = fma2(qp.x, kp.y, accA[1]);
                accA[2] = fma2(qp.y, kp.x, accA[2]); accA[3] = fma2(qp.y, kp.y, accA[3]);
            }
        }
        __syncthreads();
    }

    // horizontal-reduce pairs and store partials
    if (tileA < 392) {
        float* base = g_att_part + (((size_t)n*TCH + chunk)*SS + sA)*729;
        float a0,b0; upk(accA[0],a0,b0); base[uA*27+vA] = a0+b0;
        float a1,b1; upk(accA[1],a1,b1);
        float a2,b2; upk(accA[2],a2,b2);
        float a3,b3; upk(accA[3],a3,b3);
        if (vA+1 < 27)              base[uA*27+vA+1]     = a1+b1;
        if (uA+1 < 27)              base[(uA+1)*27+vA]   = a2+b2;
        if (uA+1 < 27 && vA+1 < 27) base[(uA+1)*27+vA+1] = a3+b3;
    }
}

// ---------------------------------------------------------------------------
// Kernel B: reduce chunks + tanh/alpha/att0
// ---------------------------------------------------------------------------
__global__ void __launch_bounds__(256) k_att_final(const float* __restrict__ alphas,
                                                   const float* __restrict__ att0) {
    int idx = blockIdx.x*256 + threadIdx.x;
    if (idx >= NN*SS*729) return;
    int n = idx / (SS*729);
    int r = idx - n*(SS*729);
    int s = r / 729;
    int uv = r - s*729;
    float sum = 0.f;
    #pragma unroll
    for (int ch = 0; ch < TCH; ++ch)
        sum += g_att_part[(((size_t)n*TCH + ch)*SS + s)*729 + uv];
    g_att[idx] = tanhf(sum * (1.0f/6400.f)) * alphas[s] + att0[s*729 + uv];
}

// ---------------------------------------------------------------------------
// Kernel C: xa = x@att ; h = lrelu(x + bn(W_out xa)) ; y2 = lrelu(x + bn(W_ff h))
// grid (200, NN), 512 threads, 2 t per block. R11 structure; ONLY change:
// x staged transposed [u][c] (row stride 66 ull, 16B-aligned) so the xa
// stage reads 8 c via 4 uniform LDS.128 instead of 8 scalar LDS.64.
// ---------------------------------------------------------------------------
__global__ void __launch_bounds__(512,2) k_main(const float* __restrict__ x,
        const float* __restrict__ W_out, const float* __restrict__ b_out,
        const float* __restrict__ g_out, const float* __restrict__ be_out,
        const float* __restrict__ m_out, const float* __restrict__ v_out,
        const float* __restrict__ W_ff,  const float* __restrict__ b_ff,
        const float* __restrict__ g_ff,  const float* __restrict__ be_ff,
        const float* __restrict__ m_ff,  const float* __restrict__ v_ff) {
    extern __shared__ ull smU[];
    ull* sWoP = smU;                      // 4096  ([j][op] pk{W[2op][j],W[2op+1][j]})
    ull* sWfP = sWoP + 4096;              // 2048
    ull* sx2T = sWfP + 2048;              // 1848  [u=27 rows of 66][c=64] pk{x[t0],x[t1]}
    float* sxaF = (float*)(sx2T + 1848);  // 7168  ([j][tt][v] scalars; reused for h)
    float* satt = sxaF + 7168;            // 1458
    float* sscale_o = satt + 1458;
    float* sshift_o = sscale_o + 64;
    float* sscale_f = sshift_o + 64;
    float* sshift_f = sscale_f + 64;

    int n = blockIdx.y, tb = blockIdx.x;
    int tid = threadIdx.x, og = tid >> 5, vv = tid & 31;
    int t0 = tb*2;

    for (int idx = tid; idx < 4096; idx += 512) {
        int op = idx & 31, j = idx >> 5;
        sWoP[idx] = pk(W_out[(2*op)*128 + j], W_out[(2*op+1)*128 + j]);
    }
    for (int idx = tid; idx < 2048; idx += 512) {
        int op = idx & 31, j = idx >> 5;
        sWfP[idx] = pk(W_ff[(2*op)*64 + j], W_ff[(2*op+1)*64 + j]);
    }
    for (int i = tid; i < 1458; i += 512) satt[i] = g_att[(size_t)n*1458 + i];
    if (tid < 64) {
        float sc = g_out[tid]*rsqrtf(v_out[tid]+EPSS);
        sscale_o[tid] = sc;
        sshift_o[tid] = be_out[tid] + sc*(b_out[tid]-m_out[tid]);
        float sf = g_ff[tid]*rsqrtf(v_ff[tid]+EPSS);
        sscale_f[tid] = sf;
        sshift_f[tid] = be_ff[tid] + sf*(b_ff[tid]-m_ff[tid]);
    }
    // stage x transposed + t-pair packed: sx2T[u*66+c] = {x[c][t0], x[c][t0+1]}
    for (int i = tid; i < 3456; i += 512) {
        int c = i / 54, r = i - c*54, tt = r / 27, u = r - tt*27;
        ((float*)sx2T)[2*(u*66+c) + tt] = x[(((size_t)n*64 + c)*400 + t0 + tt)*27 + u];
    }
    __syncthreads();

    // xa stage: t-packed; 8 c per thread via 4 uniform LDS.128; att per-lane
    if (vv < 27) {
        int s = og >> 3, c0 = (og & 7)*8;
        ull a[8] = {};
        #pragma unroll 3
        for (int u = 0; u < 27; ++u) {
            float av = satt[s*729 + u*27 + vv];
            ull av2 = pk(av, av);
            const ull* xr = sx2T + u*66 + c0;     // c0 multiple of 8 -> 16B-aligned
            ulonglong2 xA = lds128(xr);
            ulonglong2 xB = lds128(xr + 2);
            ulonglong2 xC = lds128(xr + 4);
            ulonglong2 xD = lds128(xr + 6);
            a[0] = fma2(xA.x, av2, a[0]);
            a[1] = fma2(xA.y, av2, a[1]);
            a[2] = fma2(xB.x, av2, a[2]);
            a[3] = fma2(xB.y, av2, a[3]);
            a[4] = fma2(xC.x, av2, a[4]);
            a[5] = fma2(xC.y, av2, a[5]);
            a[6] = fma2(xD.x, av2, a[6]);
            a[7] = fma2(xD.y, av2, a[7]);
        }
        #pragma unroll
        for (int ci = 0; ci < 8; ++ci) {
            int j = s*64 + c0 + ci;
            float f0, f1; upk(a[ci], f0, f1);
            sxaF[(j*2)*28 + vv]   = f0;
            sxaF[(j*2+1)*28 + vv] = f1;
        }
    }
    __syncthreads();

    // W_out stage: o-packed accumulators acc[opl][tt]; weight pair = 1 LDS.128
    float hv[2][2][2];   // [opl][tt][even/odd o]
    {
        ull acc[2][2] = {};
        if (vv < 27) {
            #pragma unroll 4
            for (int j = 0; j < 128; ++j) {
                float a0 = sxaF[(j*2)*28 + vv], a1 = sxaF[(j*2+1)*28 + vv];
                ull b0 = pk(a0, a0), b1 = pk(a1, a1);
                ulonglong2 w = lds128(sWoP + j*32 + og*2);  // 16B-aligned
                acc[0][0] = fma2(w.x, b0, acc[0][0]);
                acc[0][1] = fma2(w.x, b1, acc[0][1]);
                acc[1][0] = fma2(w.y, b0, acc[1][0]);
                acc[1][1] = fma2(w.y, b1, acc[1][1]);
            }
            #pragma unroll
            for (int opl = 0; opl < 2; ++opl) {
                int o0 = og*4 + opl*2;
                float sc0 = sscale_o[o0],   sh0 = sshift_o[o0];
                float sc1 = sscale_o[o0+1], sh1 = sshift_o[o0+1];
                float x00, x01, x10, x11;
                upk(sx2T[vv*66 + o0],     x00, x01);   // {x[o0][t0], x[o0][t1]}
                upk(sx2T[vv*66 + o0 + 1], x10, x11);
                #pragma unroll
                for (int tt = 0; tt < 2; ++tt) {
                    float f0, f1; upk(acc[opl][tt], f0, f1);
                    float xv0 = (tt == 0) ? x00 : x01;
                    float xv1 = (tt == 0) ? x10 : x11;
                    float v0 = xv0 + f0*sc0 + sh0; v0 = fmaxf(v0, LEAKK*v0);
                    float v1 = xv1 + f1*sc1 + sh1; v1 = fmaxf(v1, LEAKK*v1);
                    hv[opl][tt][0] = v0; hv[opl][tt][1] = v1;
                }
            }
        }
    }
    __syncthreads();          // all sxa reads done
    if (vv < 27) {
        #pragma unroll
        for (int opl = 0; opl < 2; ++opl) {
            int o0 = og*4 + opl*2;
            #pragma unroll
            for (int tt = 0; tt < 2; ++tt) {
                sxaF[(o0*2+tt)*28 + vv]     = hv[opl][tt][0];
                sxaF[((o0+1)*2+tt)*28 + vv] = hv[opl][tt][1];
            }
        }
    }
    __syncthreads();

    // W_ff stage -> y2 (global)
    if (vv < 27) {
        ull acc[2][2] = {};
        #pragma unroll 4
        for (int j = 0; j < 64; ++j) {
            float a0 = sxaF[(j*2)*28 + vv], a1 = sxaF[(j*2+1)*28 + vv];
            ull b0 = pk(a0, a0), b1 = pk(a1, a1);
            ulonglong2 w = lds128(sWfP + j*32 + og*2);      // 16B-aligned
            acc[0][0] = fma2(w.x, b0, acc[0][0]);
            acc[0][1] = fma2(w.x, b1, acc[0][1]);
            acc[1][0] = fma2(w.y, b0, acc[1][0]);
            acc[1][1] = fma2(w.y, b1, acc[1][1]);
        }
        #pragma unroll
        for (int opl = 0; opl < 2; ++opl) {
            int o0 = og*4 + opl*2;
            float sc0 = sscale_f[o0],   sh0 = sshift_f[o0];
            float sc1 = sscale_f[o0+1], sh1 = sshift_f[o0+1];
            float x00, x01, x10, x11;
            upk(sx2T[vv*66 + o0],     x00, x01);
            upk(sx2T[vv*66 + o0 + 1], x10, x11);
            #pragma unroll
            for (int tt = 0; tt < 2; ++tt) {
                float f0, f1; upk(acc[opl][tt], f0, f1);
                float xv0 = (tt == 0) ? x00 : x01;
                float xv1 = (tt == 0) ? x10 : x11;
                float v0 = xv0 + f0*sc0 + sh0; v0 = fmaxf(v0, LEAKK*v0);
                float v1 = xv1 + f1*sc1 + sh1; v1 = fmaxf(v1, LEAKK*v1);
                size_t row = (size_t)(n*400 + t0 + tt)*1792;
                g_y2[row + o0*28 + vv]     = v0;
                g_y2[row + (o0+1)*28 + vv] = v1;
            }
        }
    }
}

// ---------------------------------------------------------------------------
// Kernel D: z = lrelu(y2 + bn(conv_t(y2) + b_t)); 6 t per block, o-packed.
// grid (67, NN), 512 threads. Weight opl-pair fused to LDS.128 per tap.
// ---------------------------------------------------------------------------
__global__ void __launch_bounds__(512,2) k_temporal(const float* __restrict__ W_t,
        const float* __restrict__ b_t, const float* __restrict__ g_t,
        const float* __restrict__ be_t, const float* __restrict__ m_t,
        const float* __restrict__ v_t, float* __restrict__ out) {
    extern __shared__ ull smU[];
    ull* sWtP = smU;                        // 6144  ([(i*3+tap)][op] o-pairs)
    float* tile   = (float*)(sWtP + 6144);  // 8 * 1792
    float* sscale = tile + 8*1792;
    float* sshift = sscale + 64;

    int n = blockIdx.y, tb = blockIdx.x;
    int tid = threadIdx.x, og = tid >> 5, vv = tid & 31;
    int t0 = tb*TBD;

    for (int idx = tid; idx < 6144; idx += 512) {
        int op = idx & 31, r = idx >> 5;     // r = i*3+tap
        sWtP[idx] = pk(W_t[(2*op)*192 + r], W_t[(2*op+1)*192 + r]);
    }
    if (tid < 64) {
        float sc = g_t[tid]*rsqrtf(v_t[tid]+EPSS);
        sscale[tid] = sc;
        sshift[tid] = be_t[tid] + sc*(b_t[tid]-m_t[tid]);
    }
    #pragma unroll
    for (int k = 0; k < TBD+2; ++k) {
        int t = t0 - 1 + k;
        ull* dst = (ull*)(tile + k*1792);
        if (t >= 0 && t < 400) {
            const ull* src = (const ull*)(g_y2 + ((size_t)n*400 + t)*1792);
            for (int i = tid; i < 896; i += 512) dst[i] = src[i];
        } else {
            for (int i = tid; i < 896; i += 512) dst[i] = 0ULL;
        }
    }
    __syncthreads();

    if (vv < 27) {
        ull acc[2][TBD] = {};
        #pragma unroll 2
        for (int i = 0; i < 64; ++i) {
            ull bp[TBD+2];
            #pragma unroll
            for (int k = 0; k < TBD+2; ++k) {
                float a = tile[k*1792 + i*28 + vv];
                bp[k] = pk(a, a);
            }
            // per tap: one LDS.128 yields both opl weights (16B-aligned: og*2 even)
            #pragma unroll
            for (int tap = 0; tap < 3; ++tap) {
                ulonglong2 w = lds128(sWtP + (i*3+tap)*32 + og*2);
                #pragma unroll
                for (int tt = 0; tt < TBD; ++tt) {
                    acc[0][tt] = fma2(w.x, bp[tap+tt], acc[0][tt]);
                    acc[1][tt] = fma2(w.y, bp[tap+tt], acc[1][tt]);
                }
            }
        }
        #pragma unroll
        for (int opl = 0; opl < 2; ++opl) {
            int o0 = og*4 + opl*2;
            float sc0 = sscale[o0],   sh0 = sshift[o0];
            float sc1 = sscale[o0+1], sh1 = sshift[o0+1];
            size_t ob0 = ((size_t)n*64 + o0)*400;
            size_t ob1 = ((size_t)n*64 + o0+1)*400;
            #pragma unroll
            for (int tt = 0; tt < TBD; ++tt) {
                if (t0 + tt >= 400) break;
                float f0, f1; upk(acc[opl][tt], f0, f1);
                float y0 = tile[(tt+1)*1792 + o0*28 + vv];
                float y1 = tile[(tt+1)*1792 + (o0+1)*28 + vv];
                float v0 = y0 + f0*sc0 + sh0; v0 = fmaxf(v0, LEAKK*v0);
                float v1 = y1 + f1*sc1 + sh1; v1 = fmaxf(v1, LEAKK*v1);
                out[(ob0 + t0 + tt)*27 + vv] = v0;
                out[(ob1 + t0 + tt)*27 + vv] = v1;
            }
        }
    }
}

// ---------------------------------------------------------------------------
extern "C" void kernel_launch(void* const* d_in, const int* in_sizes, int n_in,
                              void* d_out, int out_size) {
    const float* x      = (const float*)d_in[0];
    const float* pe     = (const float*)d_in[1];
    const float* W_in   = (const float*)d_in[2];
    const float* b_in   = (const float*)d_in[3];
    const float* alphas = (const float*)d_in[4];
    const float* att0   = (const float*)d_in[5];
    const float* W_out  = (const float*)d_in[6];
    const float* b_out  = (const float*)d_in[7];
    const float* g_out  = (const float*)d_in[8];
    const float* be_out = (const float*)d_in[9];
    const float* m_out  = (const float*)d_in[10];
    const float* v_out  = (const float*)d_in[11];
    const float* W_ff   = (const float*)d_in[12];
    const float* b_ff   = (const float*)d_in[13];
    const float* g_ff   = (const float*)d_in[14];
    const float* be_ff  = (const float*)d_in[15];
    const float* m_ff   = (const float*)d_in[16];
    const float* v_ff   = (const float*)d_in[17];
    const float* W_t    = (const float*)d_in[18];
    const float* b_t    = (const float*)d_in[19];
    const float* g_t    = (const float*)d_in[20];
    const float* be_t   = (const float*)d_in[21];
    const float* m_t    = (const float*)d_in[22];
    const float* v_t    = (const float*)d_in[23];
    float* out = (float*)d_out;

    const int smemA = 7680*8 + 64*4;                               // 61,696 B
    const int smemC = (4096+2048+1848)*8 + (7168+1458+256)*4;      //  99,464 B
    const int smemD = 6144*8 + (8*1792 + 128)*4;                   // 107,008 B
    cudaFuncSetAttribute(k_att_part, cudaFuncAttributeMaxDynamicSharedMemorySize, smemA);
    cudaFuncSetAttribute(k_main,     cudaFuncAttributeMaxDynamicSharedMemorySize, smemC);
    cudaFuncSetAttribute(k_temporal, cudaFuncAttributeMaxDynamicSharedMemorySize, smemD);

    k_att_part<<<dim3(TCH, NN), 512, smemA>>>(x, pe, W_in, b_in);
    k_att_final<<<(NN*SS*729 + 255)/256, 256>>>(alphas, att0);
    k_main<<<dim3(TT/2, NN), 512, smemC>>>(x, W_out, b_out, g_out, be_out, m_out, v_out,
                                           W_ff, b_ff, g_ff, be_ff, m_ff, v_ff);
    k_temporal<<<dim3(NBD, NN), 512, smemD>>>(W_t, b_t, g_t, be_t, m_t, v_t, out);
}

// round 17
// speedup vs baseline: 1.3478x; 1.1948x over previous
#include <cuda_runtime.h>

#define NN 32
#define CC 64
#define TT 400
#define VV 27
#define SS 2
#define OO 64
#define LEAKK 0.1f
#define EPSS 1e-5f

#define TCH 25            // t-chunks for kernel A (16 t each, 8 pairs)
#define TBD 6             // t per block, kernel D
#define NBD ((TT + TBD - 1)/TBD)   // 67

typedef unsigned long long ull;

__device__ __forceinline__ ull fma2(ull a, ull b, ull c) {
    ull d;
    asm("fma.rn.f32x2 %0, %1, %2, %3;" : "=l"(d) : "l"(a), "l"(b), "l"(c));
    return d;
}
__device__ __forceinline__ ull pk(float lo, float hi) {
    ull r;
    asm("mov.b64 %0, {%1, %2};" : "=l"(r) : "f"(lo), "f"(hi));
    return r;
}
__device__ __forceinline__ void upk(ull v, float& lo, float& hi) {
    asm("mov.b64 {%0, %1}, %2;" : "=f"(lo), "=f"(hi) : "l"(v));
}
// 16B shared load of two packed pairs
__device__ __forceinline__ ulonglong2 lds128(const ull* p) {
    return *reinterpret_cast<const ulonglong2*>(p);
}

// Scratch (static device globals — allocation-free)
__device__ float g_att_part[NN*TCH*SS*VV*VV];
__device__ float g_att[NN*SS*VV*VV];
__device__ float g_y2[(size_t)NN*TT*1792];      // [n][t][c*28+v], padded

// Prepacked o-pair weights for k_main (filled by k_prep each launch)
__device__ __align__(16) ull gWoP[4096];        // [j=128][op=32] = pk{W_out[2op][j], W_out[2op+1][j]}
__device__ __align__(16) ull gWfP[2048];        // [j=64][op=32]

// ---------------------------------------------------------------------------
// Kernel P: prepack W_out / W_ff into o-pair ull layout in GMEM
// ---------------------------------------------------------------------------
__global__ void __launch_bounds__(256) k_prep(const float* __restrict__ W_out,
                                              const float* __restrict__ W_ff) {
    int idx = blockIdx.x*256 + threadIdx.x;
    if (idx < 4096) {
        int op = idx & 31, j = idx >> 5;
        gWoP[idx] = pk(W_out[(2*op)*128 + j], W_out[(2*op+1)*128 + j]);
    } else if (idx < 6144) {
        int i2 = idx - 4096;
        int op = i2 & 31, j = i2 >> 5;
        gWfP[i2] = pk(W_ff[(2*op)*64 + j], W_ff[(2*op+1)*64 + j]);
    }
}

// ---------------------------------------------------------------------------
// Kernel A: y = x + pe ; qk = W_in*y + b_in ; partial att accum over 16 t
// grid (25, NN), 512 threads (16 og x 4 outputs). Packed over t-pairs.
// ---------------------------------------------------------------------------
__global__ void __launch_bounds__(512,2) k_att_part(const float* __restrict__ x,
                                                    const float* __restrict__ pe,
                                                    const float* __restrict__ W_in,
                                                    const float* __restrict__ b_in) {
    extern __shared__ ull smU[];
    ull* sW2  = smU;            // 4096  (dup W_in, [c][o])
    ull* sy2  = sW2 + 4096;     // 1792  ([c][v] t-pair)
    ull* sqk2 = sy2 + 1792;     // 1792  ([o][v] t-pair)
    float* sb = (float*)(sqk2 + 1792);  // 64

    int n = blockIdx.y, chunk = blockIdx.x;
    int tid = threadIdx.x, og = tid >> 5, vv = tid & 31;

    for (int i = tid; i < 4096; i += 512) {
        int o = i & 63, c = i >> 6;
        float w = W_in[o*64 + c];
        sW2[i] = pk(w, w);
    }
    if (tid < 64) sb[tid] = b_in[tid];

    // att tiles: 2 s * 14 u2 * 14 v2 = 392 tiles of 2x2 (u,v); one per thread
    ull accA[4] = {0,0,0,0};
    int tileA = tid;                 // valid < 392
    int sA = tileA / 196; int rA = tileA - sA*196;
    int uA = (rA/14)*2, vA = (rA%14)*2;

    __syncthreads();

    for (int it = 0; it < 8; ++it) {
        int t0 = chunk*16 + it*2;
        for (int i = tid; i < 3456; i += 512) {
            int c = i / 54, r = i - c*54, tt = r / 27, v = r - tt*27;
            float val = x[(((size_t)n*64 + c)*400 + t0 + tt)*27 + v]
                      + pe[((size_t)c*400 + t0 + tt)*27 + v];
            ((float*)sy2)[2*(c*28 + v) + tt] = val;
        }
        __syncthreads();

        // projection: qk[o][vv] packed pair; 4 outputs per thread
        if (vv < 27) {
            ull acc[4];
            #pragma unroll
            for (int io = 0; io < 4; ++io) { float b = sb[og*4+io]; acc[io] = pk(b, b); }
            #pragma unroll 4
            for (int c = 0; c < 64; ++c) {
                ull yp = sy2[c*28 + vv];
                const ull* wrow = sW2 + c*64 + og*4;     // 16B-aligned
                ulonglong2 wA = lds128(wrow);
                ulonglong2 wB = lds128(wrow + 2);
                acc[0] = fma2(wA.x, yp, acc[0]);
                acc[1] = fma2(wA.y, yp, acc[1]);
                acc[2] = fma2(wB.x, yp, acc[2]);
                acc[3] = fma2(wB.y, yp, acc[3]);
            }
            #pragma unroll
            for (int io = 0; io < 4; ++io) sqk2[(og*4+io)*28 + vv] = acc[io];
        } else if (vv == 27) {
            // zero pad column so u+1 / v+1 loads are safe
            #pragma unroll
            for (int io = 0; io < 4; ++io) sqk2[(og*4+io)*28 + 27] = 0ULL;
        }
        __syncthreads();

        // q.k per 2x2 (u,v) tile; uA/vA even so pairs are 16B-aligned
        if (tileA < 392) {
            const ull* q  = sqk2 + (sA*16)*28;
            const ull* kk = sqk2 + (32 + sA*16)*28;
            #pragma unroll 4
            for (int c = 0; c < 16; ++c) {
                ulonglong2 qp = lds128(q  + c*28 + uA);
                ulonglong2 kp = lds128(kk + c*28 + vA);
                accA[0] = fma2(qp.x, kp.x, accA[0]); accA[1] = fma2(qp.x, kp.y, accA[1]);
                accA[2] = fma2(qp.y, kp.x, accA[2]); accA[3] = fma2(qp.y, kp.y, accA[3]);
            }
        }
        __syncthreads();
    }

    // horizontal-reduce pairs and store partials
    if (tileA < 392) {
        float* base = g_att_part + (((size_t)n*TCH + chunk)*SS + sA)*729;
        float a0,b0; upk(accA[0],a0,b0); base[uA*27+vA] = a0+b0;
        float a1,b1; upk(accA[1],a1,b1);
        float a2,b2; upk(accA[2],a2,b2);
        float a3,b3; upk(accA[3],a3,b3);
        if (vA+1 < 27)              base[uA*27+vA+1]     = a1+b1;
        if (uA+1 < 27)              base[(uA+1)*27+vA]   = a2+b2;
        if (uA+1 < 27 && vA+1 < 27) base[(uA+1)*27+vA+1] = a3+b3;
    }
}

// ---------------------------------------------------------------------------
// Kernel B: reduce chunks + tanh/alpha/att0
// ---------------------------------------------------------------------------
__global__ void __launch_bounds__(256) k_att_final(const float* __restrict__ alphas,
                                                   const float* __restrict__ att0) {
    int idx = blockIdx.x*256 + threadIdx.x;
    if (idx >= NN*SS*729) return;
    int n = idx / (SS*729);
    int r = idx - n*(SS*729);
    int s = r / 729;
    int uv = r - s*729;
    float sum = 0.f;
    #pragma unroll
    for (int ch = 0; ch < TCH; ++ch)
        sum += g_att_part[(((size_t)n*TCH + ch)*SS + s)*729 + uv];
    g_att[idx] = tanhf(sum * (1.0f/6400.f)) * alphas[s] + att0[s*729 + uv];
}

// ---------------------------------------------------------------------------
// Kernel C: xa = x@att ; h = lrelu(x + bn(W_out xa)) ; y2 = lrelu(x + bn(W_ff h))
// grid (100, NN), 512 threads, 4 t per block (2 t-pairs).
// Weights from GMEM (prepacked o-pairs, uniform __ldg, L1-resident).
// xa/h stored t-pair packed (ull): W inner loop = 1 LDS.64 act + 2 LDG.128
// weights + 8 fma2 per j (16 MAC). Thread map: W stages og=oc(3b)|tp(1b),
// xa og=s(1b)|oct(3b). Arithmetic order identical to R11.
// ---------------------------------------------------------------------------
__global__ void __launch_bounds__(512,2) k_main(const float* __restrict__ x,
        const float* __restrict__ b_out,
        const float* __restrict__ g_out, const float* __restrict__ be_out,
        const float* __restrict__ m_out, const float* __restrict__ v_out,
        const float* __restrict__ b_ff,
        const float* __restrict__ g_ff,  const float* __restrict__ be_ff,
        const float* __restrict__ m_ff,  const float* __restrict__ v_ff) {
    extern __shared__ ull smU[];
    ull* sx2  = smU;                      // 3584: [tp=2][c=64][u=28] pk{x[t0+2tp], x[t0+2tp+1]}
    ull* sxaU = sx2 + 3584;               // 7168: [j=128][tp=2][v=28] t-pair packed; h reuses
    float* satt = (float*)(sxaU + 7168);  // 1458
    float* sscale_o = satt + 1458;
    float* sshift_o = sscale_o + 64;
    float* sscale_f = sshift_o + 64;
    float* sshift_f = sscale_f + 64;

    int n = blockIdx.y, tb = blockIdx.x;
    int tid = threadIdx.x, og = tid >> 5, vv = tid & 31;
    int t0 = tb*4;

    // stage x t-pair packed (streaming loads, don't pollute L1)
    for (int i = tid; i < 6912; i += 512) {
        int t = i / 1728, r = i - t*1728, c = r / 27, u = r - c*27;
        ((float*)sx2)[(t>>1)*3584 + 2*(c*28+u) + (t&1)] =
            __ldcs(&x[(((size_t)n*64 + c)*400 + t0 + t)*27 + u]);
    }
    for (int i = tid; i < 1458; i += 512) satt[i] = __ldcs(&g_att[(size_t)n*1458 + i]);
    if (tid < 64) {
        float sc = g_out[tid]*rsqrtf(v_out[tid]+EPSS);
        sscale_o[tid] = sc;
        sshift_o[tid] = be_out[tid] + sc*(b_out[tid]-m_out[tid]);
        float sf = g_ff[tid]*rsqrtf(v_ff[tid]+EPSS);
        sscale_f[tid] = sf;
        sshift_f[tid] = be_ff[tid] + sf*(b_ff[tid]-m_ff[tid]);
    }
    __syncthreads();

    // xa stage: og = s(1b)|oct(3b); 8 c per thread, both t-pairs sequentially.
    // x loads warp-uniform broadcast; att per-lane. Output stays t-pair packed.
    if (vv < 27) {
        int s = og >> 3, c0 = (og & 7)*8;
        #pragma unroll
        for (int tp = 0; tp < 2; ++tp) {
            const ull* xb = sx2 + tp*1792;
            ull a[8] = {};
            #pragma unroll 3
            for (int u = 0; u < 27; ++u) {
                float av = satt[s*729 + u*27 + vv];
                ull av2 = pk(av, av);
                #pragma unroll
                for (int ci = 0; ci < 8; ++ci)
                    a[ci] = fma2(xb[(c0+ci)*28 + u], av2, a[ci]);
            }
            #pragma unroll
            for (int ci = 0; ci < 8; ++ci) {
                int j = s*64 + c0 + ci;
                sxaU[(j*2 + tp)*28 + vv] = a[ci];
            }
        }
    }
    __syncthreads();

    // W_out stage: og = oc(3b)|tp(1b); 8 o (4 o-pairs) x 1 t-pair per thread.
    int oc = og >> 1, tp = og & 1;
    float hv[8][2];     // [o within octet][tt]
    if (vv < 27) {
        ull acc[4][2] = {};
        #pragma unroll 4
        for (int j = 0; j < 128; ++j) {
            float a0, a1; upk(sxaU[(j*2 + tp)*28 + vv], a0, a1);
            ull b0 = pk(a0, a0), b1 = pk(a1, a1);
            const ulonglong2* wp = reinterpret_cast<const ulonglong2*>(gWoP + j*32 + oc*4);
            ulonglong2 wA = __ldg(wp), wB = __ldg(wp + 1);
            acc[0][0] = fma2(wA.x, b0, acc[0][0]); acc[0][1] = fma2(wA.x, b1, acc[0][1]);
            acc[1][0] = fma2(wA.y, b0, acc[1][0]); acc[1][1] = fma2(wA.y, b1, acc[1][1]);
            acc[2][0] = fma2(wB.x, b0, acc[2][0]); acc[2][1] = fma2(wB.x, b1, acc[2][1]);
            acc[3][0] = fma2(wB.y, b0, acc[3][0]); acc[3][1] = fma2(wB.y, b1, acc[3][1]);
        }
        #pragma unroll
        for (int p = 0; p < 4; ++p) {
            int o0 = oc*8 + 2*p;
            float x00, x01; upk(sx2[tp*1792 + o0*28 + vv],     x00, x01);
            float x10, x11; upk(sx2[tp*1792 + (o0+1)*28 + vv], x10, x11);
            float sc0 = sscale_o[o0],   sh0 = sshift_o[o0];
            float sc1 = sscale_o[o0+1], sh1 = sshift_o[o0+1];
            #pragma unroll
            for (int tt = 0; tt < 2; ++tt) {
                float f0, f1; upk(acc[p][tt], f0, f1);
                float xv0 = tt ? x01 : x00;
                float xv1 = tt ? x11 : x10;
                float v0 = xv0 + f0*sc0 + sh0; v0 = fmaxf(v0, LEAKK*v0);
                float v1 = xv1 + f1*sc1 + sh1; v1 = fmaxf(v1, LEAKK*v1);
                hv[2*p][tt]   = v0;
                hv[2*p+1][tt] = v1;
            }
        }
    }
    __syncthreads();          // all sxaU reads done
    if (vv < 27) {
        #pragma unroll
        for (int k = 0; k < 8; ++k) {
            int o = oc*8 + k;
            sxaU[(o*2 + tp)*28 + vv] = pk(hv[k][0], hv[k][1]);
        }
    }
    __syncthreads();

    // W_ff stage -> y2 (global). Same mapping.
    if (vv < 27) {
        ull acc[4][2] = {};
        #pragma unroll 4
        for (int j = 0; j < 64; ++j) {
            float a0, a1; upk(sxaU[(j*2 + tp)*28 + vv], a0, a1);
            ull b0 = pk(a0, a0), b1 = pk(a1, a1);
            const ulonglong2* wp = reinterpret_cast<const ulonglong2*>(gWfP + j*32 + oc*4);
            ulonglong2 wA = __ldg(wp), wB = __ldg(wp + 1);
            acc[0][0] = fma2(wA.x, b0, acc[0][0]); acc[0][1] = fma2(wA.x, b1, acc[0][1]);
            acc[1][0] = fma2(wA.y, b0, acc[1][0]); acc[1][1] = fma2(wA.y, b1, acc[1][1]);
            acc[2][0] = fma2(wB.x, b0, acc[2][0]); acc[2][1] = fma2(wB.x, b1, acc[2][1]);
            acc[3][0] = fma2(wB.y, b0, acc[3][0]); acc[3][1] = fma2(wB.y, b1, acc[3][1]);
        }
        #pragma unroll
        for (int p = 0; p < 4; ++p) {
            int o0 = oc*8 + 2*p;
            float x00, x01; upk(sx2[tp*1792 + o0*28 + vv],     x00, x01);
            float x10, x11; upk(sx2[tp*1792 + (o0+1)*28 + vv], x10, x11);
            float sc0 = sscale_f[o0],   sh0 = sshift_f[o0];
            float sc1 = sscale_f[o0+1], sh1 = sshift_f[o0+1];
            #pragma unroll
            for (int tt = 0; tt < 2; ++tt) {
                float f0, f1; upk(acc[p][tt], f0, f1);
                float xv0 = tt ? x01 : x00;
                float xv1 = tt ? x11 : x10;
                float v0 = xv0 + f0*sc0 + sh0; v0 = fmaxf(v0, LEAKK*v0);
                float v1 = xv1 + f1*sc1 + sh1; v1 = fmaxf(v1, LEAKK*v1);
                size_t row = (size_t)(n*400 + t0 + tp*2 + tt)*1792;
                g_y2[row + o0*28 + vv]     = v0;
                g_y2[row + (o0+1)*28 + vv] = v1;
            }
        }
    }
}

// ---------------------------------------------------------------------------
// Kernel D: z = lrelu(y2 + bn(conv_t(y2) + b_t)); 6 t per block, o-packed.
// grid (67, NN), 512 threads. Weight opl-pair fused to LDS.128 per tap.
// ---------------------------------------------------------------------------
__global__ void __launch_bounds__(512,2) k_temporal(const float* __restrict__ W_t,
        const float* __restrict__ b_t, const float* __restrict__ g_t,
        const float* __restrict__ be_t, const float* __restrict__ m_t,
        const float* __restrict__ v_t, float* __restrict__ out) {
    extern __shared__ ull smU[];
    ull* sWtP = smU;                        // 6144  ([(i*3+tap)][op] o-pairs)
    float* tile   = (float*)(sWtP + 6144);  // 8 * 1792
    float* sscale = tile + 8*1792;
    float* sshift = sscale + 64;

    int n = blockIdx.y, tb = blockIdx.x;
    int tid = threadIdx.x, og = tid >> 5, vv = tid & 31;
    int t0 = tb*TBD;

    for (int idx = tid; idx < 6144; idx += 512) {
        int op = idx & 31, r = idx >> 5;     // r = i*3+tap
        sWtP[idx] = pk(W_t[(2*op)*192 + r], W_t[(2*op+1)*192 + r]);
    }
    if (tid < 64) {
        float sc = g_t[tid]*rsqrtf(v_t[tid]+EPSS);
        sscale[tid] = sc;
        sshift[tid] = be_t[tid] + sc*(b_t[tid]-m_t[tid]);
    }
    #pragma unroll
    for (int k = 0; k < TBD+2; ++k) {
        int t = t0 - 1 + k;
        ull* dst = (ull*)(tile + k*1792);
        if (t >= 0 && t < 400) {
            const ull* src = (const ull*)(g_y2 + ((size_t)n*400 + t)*1792);
            for (int i = tid; i < 896; i += 512) dst[i] = src[i];
        } else {
            for (int i = tid; i < 896; i += 512) dst[i] = 0ULL;
        }
    }
    __syncthreads();

    if (vv < 27) {
        ull acc[2][TBD] = {};
        #pragma unroll 2
        for (int i = 0; i < 64; ++i) {
            ull bp[TBD+2];
            #pragma unroll
            for (int k = 0; k < TBD+2; ++k) {
                float a = tile[k*1792 + i*28 + vv];
                bp[k] = pk(a, a);
            }
            // per tap: one LDS.128 yields both opl weights (16B-aligned: og*2 even)
            #pragma unroll
            for (int tap = 0; tap < 3; ++tap) {
                ulonglong2 w = lds128(sWtP + (i*3+tap)*32 + og*2);
                #pragma unroll
                for (int tt = 0; tt < TBD; ++tt) {
                    acc[0][tt] = fma2(w.x, bp[tap+tt], acc[0][tt]);
                    acc[1][tt] = fma2(w.y, bp[tap+tt], acc[1][tt]);
                }
            }
        }
        #pragma unroll
        for (int opl = 0; opl < 2; ++opl) {
            int o0 = og*4 + opl*2;
            float sc0 = sscale[o0],   sh0 = sshift[o0];
            float sc1 = sscale[o0+1], sh1 = sshift[o0+1];
            size_t ob0 = ((size_t)n*64 + o0)*400;
            size_t ob1 = ((size_t)n*64 + o0+1)*400;
            #pragma unroll
            for (int tt = 0; tt < TBD; ++tt) {
                if (t0 + tt >= 400) break;
                float f0, f1; upk(acc[opl][tt], f0, f1);
                float y0 = tile[(tt+1)*1792 + o0*28 + vv];
                float y1 = tile[(tt+1)*1792 + (o0+1)*28 + vv];
                float v0 = y0 + f0*sc0 + sh0; v0 = fmaxf(v0, LEAKK*v0);
                float v1 = y1 + f1*sc1 + sh1; v1 = fmaxf(v1, LEAKK*v1);
                out[(ob0 + t0 + tt)*27 + vv] = v0;
                out[(ob1 + t0 + tt)*27 + vv] = v1;
            }
        }
    }
}

// ---------------------------------------------------------------------------
extern "C" void kernel_launch(void* const* d_in, const int* in_sizes, int n_in,
                              void* d_out, int out_size) {
    const float* x      = (const float*)d_in[0];
    const float* pe     = (const float*)d_in[1];
    const float* W_in   = (const float*)d_in[2];
    const float* b_in   = (const float*)d_in[3];
    const float* alphas = (const float*)d_in[4];
    const float* att0   = (const float*)d_in[5];
    const float* W_out  = (const float*)d_in[6];
    const float* b_out  = (const float*)d_in[7];
    const float* g_out  = (const float*)d_in[8];
    const float* be_out = (const float*)d_in[9];
    const float* m_out  = (const float*)d_in[10];
    const float* v_out  = (const float*)d_in[11];
    const float* W_ff   = (const float*)d_in[12];
    const float* b_ff   = (const float*)d_in[13];
    const float* g_ff   = (const float*)d_in[14];
    const float* be_ff  = (const float*)d_in[15];
    const float* m_ff   = (const float*)d_in[16];
    const float* v_ff   = (const float*)d_in[17];
    const float* W_t    = (const float*)d_in[18];
    const float* b_t    = (const float*)d_in[19];
    const float* g_t    = (const float*)d_in[20];
    const float* be_t   = (const float*)d_in[21];
    const float* m_t    = (const float*)d_in[22];
    const float* v_t    = (const float*)d_in[23];
    float* out = (float*)d_out;

    const int smemA = 7680*8 + 64*4;                               // 61,696 B
    const int smemC = (3584+7168)*8 + (1458+256)*4;                //  92,872 B
    const int smemD = 6144*8 + (8*1792 + 128)*4;                   // 107,008 B
    cudaFuncSetAttribute(k_att_part, cudaFuncAttributeMaxDynamicSharedMemorySize, smemA);
    cudaFuncSetAttribute(k_main,     cudaFuncAttributeMaxDynamicSharedMemorySize, smemC);
    cudaFuncSetAttribute(k_temporal, cudaFuncAttributeMaxDynamicSharedMemorySize, smemD);

    k_prep<<<24, 256>>>(W_out, W_ff);
    k_att_part<<<dim3(TCH, NN), 512, smemA>>>(x, pe, W_in, b_in);
    k_att_final<<<(NN*SS*729 + 255)/256, 256>>>(alphas, att0);
    k_main<<<dim3(TT/4, NN), 512, smemC>>>(x, b_out, g_out, be_out, m_out, v_out,
                                           b_ff, g_ff, be_ff, m_ff, v_ff);
    k_temporal<<<dim3(NBD, NN), 512, smemD>>>(W_t, b_t, g_t, be_t, m_t, v_t, out);
}